// round 16
// baseline (speedup 1.0000x reference)
#include <cuda_runtime.h>
#include <cuda_bf16.h>
#include <cstdint>

#define BB      8192
#define FF      2048
#define NRULES  512
#define GG      16
#define NPAIR   136
#define EPSV    1e-5f
#define FULLMASK 0xffffffffu

#define NCHUNK   8
#define KC       (BB / NCHUNK)    // 1024 rows per (rule,chunk) warp
#define KTILE    64               // bf16 k per smem tile
#define NT       (KC / KTILE)     // 16 tiles per warp
#define ROWSTRIDE 72              // bf16 per smem row (144B): conflict-free

// Scratch (device globals: allocation-free per harness rules)
__device__ __nv_bfloat16 g_xTh[(size_t)FF * BB];     // 32MB transposed bf16 x
__device__ float g_colsum[FF];                       // per-feature sums (fp32)
__device__ __align__(16) float g_wF[FF];             // folded GEMV weights
__device__ float g_c0;                               // folded constant

// ---------------------------------------------------------------------------
// warp-MMA helpers (plain sm_80+ PTX: compiles on compute_103, no 'a' needed)
// ---------------------------------------------------------------------------
__device__ __forceinline__ unsigned smem_u32(const void* p) {
    unsigned a;
    asm("{ .reg .u64 t; cvta.to.shared.u64 t, %1; cvt.u32.u64 %0, t; }"
        : "=r"(a) : "l"(p));
    return a;
}
__device__ __forceinline__ void ldsm_x4(unsigned& r0, unsigned& r1,
                                        unsigned& r2, unsigned& r3, unsigned addr) {
    asm volatile("ldmatrix.sync.aligned.m8n8.x4.shared.b16 {%0,%1,%2,%3}, [%4];"
                 : "=r"(r0), "=r"(r1), "=r"(r2), "=r"(r3) : "r"(addr));
}
__device__ __forceinline__ void mma16816(float* d, unsigned a0, unsigned a1,
                                         unsigned a2, unsigned a3,
                                         unsigned b0, unsigned b1) {
    asm volatile(
        "mma.sync.aligned.m16n8k16.row.col.f32.bf16.bf16.f32 "
        "{%0,%1,%2,%3}, {%4,%5,%6,%7}, {%8,%9}, {%0,%1,%2,%3};"
        : "+f"(d[0]), "+f"(d[1]), "+f"(d[2]), "+f"(d[3])
        : "r"(a0), "r"(a1), "r"(a2), "r"(a3), "r"(b0), "r"(b1));
}

// ---------------------------------------------------------------------------
// Kernel Z: zero the scatter targets every launch (graph replays reuse them)
// ---------------------------------------------------------------------------
__global__ void zero_kernel(const float* __restrict__ fc2_b) {
    int t = blockIdx.x * blockDim.x + threadIdx.x;
    if (t < FF) { g_wF[t] = 0.0f; g_colsum[t] = 0.0f; }
    if (t == 0) g_c0 = fc2_b[0];
}

// ---------------------------------------------------------------------------
// Kernel T (v2): transpose + bf16 convert + column sums; 64B x 32F blocks.
// Load: 64 batch rows x 32 features, fully coalesced 128B warp loads.
// Write: warp ty emits features 4ty..4ty+3; lane l packs batches (2l, 2l+1)
// into one bf162 -> every store is a full 128B warp transaction.
// ---------------------------------------------------------------------------
__global__ __launch_bounds__(256) void transpose_cvt_kernel(const float* __restrict__ x) {
    __shared__ float t[64][33];
    const int lane = threadIdx.x & 31;
    const int ty   = threadIdx.x >> 5;        // 0..7
    const int col0 = blockIdx.x * 32;         // F dimension
    const int row0 = blockIdx.y * 64;         // B dimension
#pragma unroll
    for (int i = 0; i < 8; i++) {
        const int r = ty * 8 + i;             // 0..63
        t[r][lane] = x[(size_t)(row0 + r) * FF + col0 + lane];
    }
    __syncthreads();
#pragma unroll
    for (int c = 0; c < 4; c++) {
        const int fc = 4 * ty + c;            // local feature
        float v0 = t[2 * lane][fc];
        float v1 = t[2 * lane + 1][fc];
        *reinterpret_cast<__nv_bfloat162*>(
            g_xTh + (size_t)(col0 + fc) * BB + row0 + 2 * lane) =
            __floats2bfloat162_rn(v0, v1);
        float s = v0 + v1;
#pragma unroll
        for (int o = 16; o > 0; o >>= 1) s += __shfl_xor_sync(FULLMASK, s, o);
        if (lane == 0) atomicAdd(&g_colsum[col0 + fc], s);
    }
}

// ---------------------------------------------------------------------------
// Kernel A (v8): FUSED tensor-core syrk + analytic BN fold. One block = rule.
// 8 warps = 8 K-chunks of 1024 rows (2x occupancy vs v7); register prefetch
// depth 2 (tile kt+2) -> 8 outstanding LDG.128 per warp.
// Symmetric B reuse: for row.col mma over B == A, b-frags ARE a-frags:
// mma(d0, a, a0,a2), mma(d1, a, a1,a3). No B ldmatrix at all.
// Epilogue: unique-owner triangle -> smem sP[chunk]; warp 0 folds + scatters.
// grid = NRULES, block = 256.
// ---------------------------------------------------------------------------
__global__ __launch_bounds__(256) void stats_fold_kernel(const int* __restrict__ idx,
                                                         const float* __restrict__ W1,
                                                         const float* __restrict__ bn1_w,
                                                         const float* __restrict__ W2,
                                                         const float* __restrict__ fc2_w) {
    __shared__ __align__(16) __nv_bfloat16 sT[NCHUNK][GG][ROWSTRIDE];
    __shared__ float sP[NCHUNK][NPAIR];   // per-chunk pair sums
    __shared__ float sW[GG][GG + 1];      // W1 rows
    __shared__ float sC[GG][GG + 1];      // covariance
    __shared__ float sCB[GG];             // W2[j]*bn1_w[j]
    __shared__ float sMu[GG];             // means (from colsum)
    __shared__ float sA[GG];              // caj
    __shared__ float sAl[GG];             // alpha

    const int tid  = threadIdx.x;
    const int wid  = tid >> 5;            // = K chunk (0..7)
    const int lane = tid & 31;
    const int n    = blockIdx.x;          // rule
    const float invB = 1.0f / (float)BB;

    // ---- prologue: fold operands staged while MMA loop runs ----
    if (tid < 64) {
        float4 v = __ldg(reinterpret_cast<const float4*>(W1 + (size_t)n * GG * GG) + tid);
        int row = tid >> 2, c = (tid & 3) * 4;
        sW[row][c]     = v.x;
        sW[row][c + 1] = v.y;
        sW[row][c + 2] = v.z;
        sW[row][c + 3] = v.w;
    } else if (tid < 80) {
        int l = tid - 64;
        sCB[l] = __ldg(W2 + n * GG + l) * __ldg(bn1_w + n * GG + l);
    } else if (tid < 96) {
        int l = tid - 80;
        sMu[l] = g_colsum[__ldg(idx + n * GG + l)] * invB;
    }

    // staging map: unit t = lane + 32*i -> row t>>3, 16B-unit t&7
    const __nv_bfloat16* srcp[4];
    __nv_bfloat16* stp[4];
#pragma unroll
    for (int i = 0; i < 4; i++) {
        const int t   = lane + 32 * i;
        const int row = t >> 3, un = t & 7;
        srcp[i] = g_xTh + (size_t)__ldg(idx + n * GG + row) * BB + wid * KC + un * 8;
        stp[i]  = &sT[wid][row][un * 8];
    }

    const unsigned sbase = smem_u32(&sT[wid][0][0]);
    const unsigned arow  = (lane & 7) + ((lane >> 3) & 1) * 8;
    const unsigned aoff  = arow * 144u + ((lane >> 4) & 1) * 16u;

    float d[2][4];
#pragma unroll
    for (int h = 0; h < 2; h++)
#pragma unroll
        for (int e = 0; e < 4; e++) d[h][e] = 0.0f;

    // depth-2 register prefetch: v[p] holds tile (kt) with p = kt&1
    uint4 v[2][4];
#pragma unroll
    for (int i = 0; i < 4; i++) {
        v[0][i] = __ldg(reinterpret_cast<const uint4*>(srcp[i]));
        v[1][i] = __ldg(reinterpret_cast<const uint4*>(srcp[i] + KTILE));
    }

#pragma unroll 1
    for (int kt = 0; kt < NT; kt++) {
        const int p = kt & 1;
        __syncwarp();
#pragma unroll
        for (int i = 0; i < 4; i++) *reinterpret_cast<uint4*>(stp[i]) = v[p][i];
        __syncwarp();
        if (kt + 2 < NT) {
#pragma unroll
            for (int i = 0; i < 4; i++)
                v[p][i] = __ldg(reinterpret_cast<const uint4*>(srcp[i] + (kt + 2) * KTILE));
        }
#pragma unroll
        for (int s = 0; s < 4; s++) {
            unsigned a0, a1, a2, a3;
            ldsm_x4(a0, a1, a2, a3, sbase + aoff + s * 32u);
            mma16816(d[0], a0, a1, a2, a3, a0, a2);   // B = rows n0..7  = {a0,a2}
            mma16816(d[1], a0, a1, a2, a3, a1, a3);   // B = rows n8..15 = {a1,a3}
        }
    }

    // ---- epilogue: unique owner per (j,k) -> smem triangle stores ----
    const int gid = lane >> 2, tig = lane & 3;
#pragma unroll
    for (int h = 0; h < 2; h++) {
#pragma unroll
        for (int e = 0; e < 4; e++) {
            const int j = gid + (e >> 1) * 8;
            const int k = h * 8 + tig * 2 + (e & 1);
            if (j <= k)
                sP[wid][16 * j - j * (j - 1) / 2 + (k - j)] = d[h][e];
        }
    }
    __syncthreads();

    // ---- fold (warp 0 only): BN1 -> W2 -> BN2 -> fc2, scatter into wF ----
    if (wid == 0) {
        const int a = lane & 15;

        // covariance: lanes split the 136 pairs; sum the 8 chunk partials
        {
            int p = 0;
#pragma unroll
            for (int j = 0; j < GG; j++) {
#pragma unroll
                for (int k = j; k < GG; k++) {
                    if ((p & 31) == lane) {
                        float s = 0.0f;
#pragma unroll
                        for (int c = 0; c < NCHUNK; c++) s += sP[c][p];
                        float cv = s * invB - sMu[j] * sMu[k];
                        sC[j][k] = cv;
                        sC[k][j] = cv;
                    }
                    p++;
                }
            }
        }
        __syncwarp();

        // lane a: varh_a = w_a^T C w_a   (broadcast smem reads, no shuffles)
        float wreg[GG];
#pragma unroll
        for (int b = 0; b < GG; b++) wreg[b] = sW[a][b];
        float varh = 0.0f;
#pragma unroll
        for (int i = 0; i < GG; i++) {
            float t = 0.0f;
#pragma unroll
            for (int b = 0; b < GG; b++) t = fmaf(sC[i][b], wreg[b], t);
            varh = fmaf(wreg[i], t, varh);
        }
        float caj = sCB[a] * rsqrtf(varh + EPSV);
        if (lane < GG) sA[a] = caj;
        __syncwarp();

        float alpha = 0.0f;
#pragma unroll
        for (int j = 0; j < GG; j++)
            alpha = fmaf(sA[j], sW[j][a], alpha);
        if (lane < GG) sAl[a] = alpha;
        __syncwarp();

        float t2 = 0.0f;
#pragma unroll
        for (int b = 0; b < GG; b++) t2 = fmaf(sC[a][b], sAl[b], t2);
        float varo = alpha * t2;
        float muoa = alpha * sMu[a];
#pragma unroll
        for (int o = 8; o > 0; o >>= 1) {
            varo += __shfl_xor_sync(FULLMASK, varo, o);
            muoa += __shfl_xor_sync(FULLMASK, muoa, o);
        }
        float sc = __ldg(fc2_w + n) * rsqrtf(varo + EPSV);

        if (lane < GG) atomicAdd(&g_wF[__ldg(idx + n * GG + lane)], sc * alpha);
        if (lane == 0) atomicAdd(&g_c0, -sc * muoa);
    }
}

// ---------------------------------------------------------------------------
// Kernel C: out[b] = x[b,:] . wF + c0   (8192x2048 GEMV, fp32 x for accuracy)
// ---------------------------------------------------------------------------
__global__ __launch_bounds__(256) void gemv_kernel(const float* __restrict__ x,
                                                   float* __restrict__ out) {
    const int warp = threadIdx.x >> 5;
    const int lane = threadIdx.x & 31;
    const int row  = blockIdx.x * 8 + warp;

    const float4* xr = reinterpret_cast<const float4*>(x + (size_t)row * FF);
    const float4* wv = reinterpret_cast<const float4*>(g_wF);

    float acc = 0.0f;
#pragma unroll
    for (int i = 0; i < 16; i++) {
        float4 a = __ldg(xr + lane + 32 * i);
        float4 w = wv[lane + 32 * i];
        acc = fmaf(a.x, w.x, acc);
        acc = fmaf(a.y, w.y, acc);
        acc = fmaf(a.z, w.z, acc);
        acc = fmaf(a.w, w.w, acc);
    }
#pragma unroll
    for (int o = 16; o > 0; o >>= 1) acc += __shfl_xor_sync(FULLMASK, acc, o);
    if (lane == 0) out[row] = acc + g_c0;
}

// ---------------------------------------------------------------------------
extern "C" void kernel_launch(void* const* d_in, const int* in_sizes, int n_in,
                              void* d_out, int out_size) {
    const float* x     = (const float*)d_in[0];
    const int*   idx   = (const int*)  d_in[1];
    const float* W1    = (const float*)d_in[2];
    // d_in[3] = b1, d_in[5] = bn1_b, d_in[7] = b2 : cancel exactly under BN
    const float* bn1_w = (const float*)d_in[4];
    const float* W2    = (const float*)d_in[6];
    const float* fc2_w = (const float*)d_in[8];
    const float* fc2_b = (const float*)d_in[9];
    float* out = (float*)d_out;

    zero_kernel<<<(FF + 255) / 256, 256>>>(fc2_b);

    dim3 tgrid(FF / 32, BB / 64);
    transpose_cvt_kernel<<<tgrid, 256>>>(x);

    stats_fold_kernel<<<NRULES, 256>>>(idx, W1, bn1_w, W2, fc2_w);

    gemv_kernel<<<BB / 8, 256>>>(x, out);
}

// round 17
// speedup vs baseline: 1.4638x; 1.4638x over previous
#include <cuda_runtime.h>
#include <cuda_bf16.h>
#include <cstdint>

#define BB      8192
#define FF      2048
#define NRULES  512
#define GG      16
#define NPAIR   136
#define EPSV    1e-5f
#define FULLMASK 0xffffffffu

#define NCHUNK   4
#define KC       (BB / NCHUNK)    // 2048 rows per (rule,chunk) warp
#define KTILE    64               // bf16 k per smem tile
#define NT       (KC / KTILE)     // 32 tiles per warp
#define ROWSTRIDE 72              // bf16 per smem row (144B): conflict-free

// Scratch (device globals: allocation-free per harness rules)
__device__ __nv_bfloat16 g_xTh[(size_t)FF * BB];     // 32MB transposed bf16 x
__device__ float g_colsum[FF];                       // per-feature sums (fp32)
__device__ float g_pair[NRULES][NCHUNK][NPAIR];      // per-rule pair products
__device__ __align__(16) float g_wF[FF];             // folded GEMV weights
__device__ float g_c0;                               // folded constant

// ---------------------------------------------------------------------------
// warp-MMA helpers (plain sm_80+ PTX: compiles on compute_103, no 'a' needed)
// ---------------------------------------------------------------------------
__device__ __forceinline__ unsigned smem_u32(const void* p) {
    unsigned a;
    asm("{ .reg .u64 t; cvta.to.shared.u64 t, %1; cvt.u32.u64 %0, t; }"
        : "=r"(a) : "l"(p));
    return a;
}
__device__ __forceinline__ void ldsm_x4(unsigned& r0, unsigned& r1,
                                        unsigned& r2, unsigned& r3, unsigned addr) {
    asm volatile("ldmatrix.sync.aligned.m8n8.x4.shared.b16 {%0,%1,%2,%3}, [%4];"
                 : "=r"(r0), "=r"(r1), "=r"(r2), "=r"(r3) : "r"(addr));
}
__device__ __forceinline__ void ldsm_x2(unsigned& r0, unsigned& r1, unsigned addr) {
    asm volatile("ldmatrix.sync.aligned.m8n8.x2.shared.b16 {%0,%1}, [%2];"
                 : "=r"(r0), "=r"(r1) : "r"(addr));
}
__device__ __forceinline__ void mma16816(float* d, unsigned a0, unsigned a1,
                                         unsigned a2, unsigned a3,
                                         unsigned b0, unsigned b1) {
    asm volatile(
        "mma.sync.aligned.m16n8k16.row.col.f32.bf16.bf16.f32 "
        "{%0,%1,%2,%3}, {%4,%5,%6,%7}, {%8,%9}, {%0,%1,%2,%3};"
        : "+f"(d[0]), "+f"(d[1]), "+f"(d[2]), "+f"(d[3])
        : "r"(a0), "r"(a1), "r"(a2), "r"(a3), "r"(b0), "r"(b1));
}

// ---------------------------------------------------------------------------
// Kernel Z: zero the scatter targets every launch (graph replays reuse them)
// ---------------------------------------------------------------------------
__global__ void zero_kernel(const float* __restrict__ fc2_b) {
    int t = blockIdx.x * blockDim.x + threadIdx.x;
    if (t < FF) { g_wF[t] = 0.0f; g_colsum[t] = 0.0f; }
    if (t == 0) g_c0 = fc2_b[0];
}

// ---------------------------------------------------------------------------
// Kernel T (v3): COARSENED transpose + bf16 convert + column sums.
// Block = 32 features x 512 batches, looping 16 sub-tiles of 32x32 with
// register double-buffering (sub-tile s+1's LDGs in flight during s's store
// phase). 1024 blocks instead of 16384 -> latency amortized over real work.
// Store map identical to the proven R14 tile: warp ty stores features
// 4ty..4ty+3, lane = batch (smem reads t[lane][fc]: conflict-free).
// Colsum: per-lane register partials, ONE warp-reduce + atomic per feature.
// ---------------------------------------------------------------------------
__global__ __launch_bounds__(256) void transpose_cvt_kernel(const float* __restrict__ x) {
    __shared__ float t[32][33];
    const int lane = threadIdx.x & 31;
    const int ty   = threadIdx.x >> 5;        // 0..7
    const int col0 = blockIdx.x * 32;         // F dimension
    const int row0 = blockIdx.y * 512;        // B dimension

    float csum[4] = {0.0f, 0.0f, 0.0f, 0.0f};
    float v[4];
#pragma unroll
    for (int i = 0; i < 4; i++)
        v[i] = x[(size_t)(row0 + ty + 8 * i) * FF + col0 + lane];

#pragma unroll 1
    for (int s = 0; s < 16; s++) {
        __syncthreads();                      // smem tile free for reuse
#pragma unroll
        for (int i = 0; i < 4; i++) t[ty + 8 * i][lane] = v[i];
        __syncthreads();
        if (s < 15) {
#pragma unroll
            for (int i = 0; i < 4; i++)
                v[i] = x[(size_t)(row0 + (s + 1) * 32 + ty + 8 * i) * FF + col0 + lane];
        }
#pragma unroll
        for (int c = 0; c < 4; c++) {
            const int fc = 4 * ty + c;        // local feature
            float val = t[lane][fc];          // batch = lane (conflict-free)
            g_xTh[(size_t)(col0 + fc) * BB + row0 + s * 32 + lane] =
                __float2bfloat16(val);
            csum[c] += val;                   // per-lane partial (no shfl here)
        }
    }
    // one reduce + atomic per feature per block
#pragma unroll
    for (int c = 0; c < 4; c++) {
        float sred = csum[c];
#pragma unroll
        for (int o = 16; o > 0; o >>= 1) sred += __shfl_xor_sync(FULLMASK, sred, o);
        if (lane == 0) atomicAdd(&g_colsum[col0 + 4 * ty + c], sred);
    }
}

// ---------------------------------------------------------------------------
// Kernel A (R14-exact): warp-level bf16 tensor-core syrk for pair moments.
// One warp = (rule n, K-chunk kc). Per 16x64 smem tile: 4 K=16 slabs, each
// A=ldmatrix.x4, B(n-half)=ldmatrix.x2, 2 MMAs. f32 accumulator frags;
// unique-owner triangle stores, no shuffles.
// block = 128 (4 warps), grid = NRULES*NCHUNK/4 = 512.
// ---------------------------------------------------------------------------
__global__ __launch_bounds__(128) void stats_mma_kernel(const int* __restrict__ idx) {
    __shared__ __align__(16) __nv_bfloat16 sT[4][GG][ROWSTRIDE];

    const int wid  = threadIdx.x >> 5;
    const int lane = threadIdx.x & 31;
    const int wg   = blockIdx.x * 4 + wid;
    const int n    = wg >> 2;                 // rule
    const int kc   = wg & 3;                  // K chunk

    // staging map: unit t = lane + 32*i -> row t>>3, 16B-unit t&7
    const __nv_bfloat16* srcp[4];
    __nv_bfloat16* stp[4];
#pragma unroll
    for (int i = 0; i < 4; i++) {
        const int t   = lane + 32 * i;
        const int row = t >> 3, un = t & 7;
        srcp[i] = g_xTh + (size_t)__ldg(idx + n * GG + row) * BB + kc * KC + un * 8;
        stp[i]  = &sT[wid][row][un * 8];
    }

    const unsigned sbase = smem_u32(&sT[wid][0][0]);
    const unsigned arow  = (lane & 7) + ((lane >> 3) & 1) * 8;
    const unsigned aoff  = arow * 144u + ((lane >> 4) & 1) * 16u;
    const unsigned brow  = (lane & 7);
    const unsigned bko   = ((lane >> 3) & 1) * 16u;

    float d[2][4];
#pragma unroll
    for (int h = 0; h < 2; h++)
#pragma unroll
        for (int e = 0; e < 4; e++) d[h][e] = 0.0f;

    uint4 v[4];
#pragma unroll
    for (int i = 0; i < 4; i++) v[i] = __ldg(reinterpret_cast<const uint4*>(srcp[i]));

#pragma unroll 1
    for (int kt = 0; kt < NT; kt++) {
        __syncwarp();
#pragma unroll
        for (int i = 0; i < 4; i++) *reinterpret_cast<uint4*>(stp[i]) = v[i];
        __syncwarp();
        if (kt + 1 < NT) {
#pragma unroll
            for (int i = 0; i < 4; i++)
                v[i] = __ldg(reinterpret_cast<const uint4*>(srcp[i] + (kt + 1) * KTILE));
        }
#pragma unroll
        for (int s = 0; s < 4; s++) {
            unsigned a0, a1, a2, a3, b0, b1;
            ldsm_x4(a0, a1, a2, a3, sbase + aoff + s * 32u);
            ldsm_x2(b0, b1, sbase + brow * 144u + bko + s * 32u);           // n 0..7
            mma16816(d[0], a0, a1, a2, a3, b0, b1);
            ldsm_x2(b0, b1, sbase + (8 + brow) * 144u + bko + s * 32u);     // n 8..15
            mma16816(d[1], a0, a1, a2, a3, b0, b1);
        }
    }

    // epilogue: unique owner per (j,k) -> direct triangle stores
    const int gid = lane >> 2, tig = lane & 3;
    float* dst = g_pair[n][kc];
#pragma unroll
    for (int h = 0; h < 2; h++) {
#pragma unroll
        for (int e = 0; e < 4; e++) {
            const int j = gid + (e >> 1) * 8;
            const int k = h * 8 + tig * 2 + (e & 1);
            if (j <= k)
                dst[16 * j - j * (j - 1) / 2 + (k - j)] = d[h][e];
        }
    }
}

// ---------------------------------------------------------------------------
// Kernel B (R14-exact): analytic BN fold, one warp per rule, lane-parallel.
// mu from g_colsum (no gather); pairs from g_pair (NCHUNK summed).
// block = 128 (4 warps = 4 rules), grid = NRULES/4.
// ---------------------------------------------------------------------------
__global__ __launch_bounds__(128) void fold_kernel(const int* __restrict__ idx,
                                                   const float* __restrict__ W1,
                                                   const float* __restrict__ bn1_w,
                                                   const float* __restrict__ W2,
                                                   const float* __restrict__ fc2_w) {
    __shared__ float sP[4][NPAIR];
    __shared__ float sMu[4][GG];
    __shared__ float sC[4][GG][GG + 1];
    __shared__ float sW[4][GG][GG + 1];
    __shared__ float sCB[4][GG];
    __shared__ float sA[4][GG];
    __shared__ float sAl[4][GG];

    const int w    = threadIdx.x >> 5;
    const int lane = threadIdx.x & 31;
    const int a    = lane & 15;
    const int n    = blockIdx.x * 4 + w;
    const float invB = 1.0f / (float)BB;

    const float4* w4 = reinterpret_cast<const float4*>(W1 + (size_t)n * GG * GG);
#pragma unroll
    for (int i = lane; i < 64; i += 32) {
        float4 v = __ldg(w4 + i);
        int row = i >> 2, c = (i & 3) * 4;
        sW[w][row][c]     = v.x;
        sW[w][row][c + 1] = v.y;
        sW[w][row][c + 2] = v.z;
        sW[w][row][c + 3] = v.w;
    }
    if (lane < GG) {
        sCB[w][lane] = __ldg(W2 + n * GG + lane) * __ldg(bn1_w + n * GG + lane);
        sMu[w][lane] = g_colsum[__ldg(idx + n * GG + lane)] * invB;
    }
    for (int q = lane; q < NPAIR; q += 32) {
        float acc = 0.0f;
#pragma unroll
        for (int c = 0; c < NCHUNK; c++) acc += g_pair[n][c][q];
        sP[w][q] = acc;
    }
    __syncwarp();

    // covariance
    {
        int p = 0;
#pragma unroll
        for (int j = 0; j < GG; j++) {
#pragma unroll
            for (int k = j; k < GG; k++) {
                if ((p & 31) == lane) {
                    float c = sP[w][p] * invB - sMu[w][j] * sMu[w][k];
                    sC[w][j][k] = c;
                    sC[w][k][j] = c;
                }
                p++;
            }
        }
    }
    __syncwarp();

    // lane a: varh_a = w_a^T C w_a
    float wreg[GG];
#pragma unroll
    for (int b = 0; b < GG; b++) wreg[b] = sW[w][a][b];
    float varh = 0.0f;
#pragma unroll
    for (int i = 0; i < GG; i++) {
        float t = 0.0f;
#pragma unroll
        for (int b = 0; b < GG; b++) t = fmaf(sC[w][i][b], wreg[b], t);
        varh = fmaf(wreg[i], t, varh);
    }
    float caj = sCB[w][a] * rsqrtf(varh + EPSV);
    if (lane < GG) sA[w][a] = caj;
    __syncwarp();

    float alpha = 0.0f;
#pragma unroll
    for (int j = 0; j < GG; j++)
        alpha = fmaf(sA[w][j], sW[w][j][a], alpha);
    if (lane < GG) sAl[w][a] = alpha;
    __syncwarp();

    float t2 = 0.0f;
#pragma unroll
    for (int b = 0; b < GG; b++) t2 = fmaf(sC[w][a][b], sAl[w][b], t2);
    float varo = alpha * t2;
    float muoa = alpha * sMu[w][a];
#pragma unroll
    for (int o = 8; o > 0; o >>= 1) {
        varo += __shfl_xor_sync(FULLMASK, varo, o);
        muoa += __shfl_xor_sync(FULLMASK, muoa, o);
    }
    float sc = __ldg(fc2_w + n) * rsqrtf(varo + EPSV);

    if (lane < GG) atomicAdd(&g_wF[__ldg(idx + n * GG + lane)], sc * alpha);
    if (lane == 0) atomicAdd(&g_c0, -sc * muoa);
}

// ---------------------------------------------------------------------------
// Kernel C (R14-exact): out[b] = x[b,:] . wF + c0   (8192x2048 GEMV)
// ---------------------------------------------------------------------------
__global__ __launch_bounds__(256) void gemv_kernel(const float* __restrict__ x,
                                                   float* __restrict__ out) {
    const int warp = threadIdx.x >> 5;
    const int lane = threadIdx.x & 31;
    const int row  = blockIdx.x * 8 + warp;

    const float4* xr = reinterpret_cast<const float4*>(x + (size_t)row * FF);
    const float4* wv = reinterpret_cast<const float4*>(g_wF);

    float acc = 0.0f;
#pragma unroll
    for (int i = 0; i < 16; i++) {
        float4 a = __ldg(xr + lane + 32 * i);
        float4 w = wv[lane + 32 * i];
        acc = fmaf(a.x, w.x, acc);
        acc = fmaf(a.y, w.y, acc);
        acc = fmaf(a.z, w.z, acc);
        acc = fmaf(a.w, w.w, acc);
    }
#pragma unroll
    for (int o = 16; o > 0; o >>= 1) acc += __shfl_xor_sync(FULLMASK, acc, o);
    if (lane == 0) out[row] = acc + g_c0;
}

// ---------------------------------------------------------------------------
extern "C" void kernel_launch(void* const* d_in, const int* in_sizes, int n_in,
                              void* d_out, int out_size) {
    const float* x     = (const float*)d_in[0];
    const int*   idx   = (const int*)  d_in[1];
    const float* W1    = (const float*)d_in[2];
    // d_in[3] = b1, d_in[5] = bn1_b, d_in[7] = b2 : cancel exactly under BN
    const float* bn1_w = (const float*)d_in[4];
    const float* W2    = (const float*)d_in[6];
    const float* fc2_w = (const float*)d_in[8];
    const float* fc2_b = (const float*)d_in[9];
    float* out = (float*)d_out;

    zero_kernel<<<(FF + 255) / 256, 256>>>(fc2_b);

    dim3 tgrid(FF / 32, BB / 512);
    transpose_cvt_kernel<<<tgrid, 256>>>(x);

    stats_mma_kernel<<<NRULES * NCHUNK / 4, 128>>>(idx);

    fold_kernel<<<NRULES / 4, 128>>>(idx, W1, bn1_w, W2, fc2_w);

    gemv_kernel<<<BB / 8, 256>>>(x, out);
}